// round 8
// baseline (speedup 1.0000x reference)
#include <cuda_runtime.h>

#define NROWS  256
#define RSLICE 8                 // reduce blocks per row
#define SCHUNK 49                // scale blocks per row (12544 float4 / 256)
#define XDIM   (RSLICE + SCHUNK) // 57

// Scratch (no cudaMalloc). __device__ globals zero-init at module load.
__device__ float d_partial[NROWS * RSLICE];
__device__ float d_row_mean[NROWS];
__device__ unsigned int d_count[NROWS];       // reduce arrival counter
__device__ volatile unsigned int d_ready[NROWS];  // mean published flag
__device__ unsigned int d_done[NROWS];        // scale completion counter

__global__ __launch_bounds__(256) void fused_pipeline_kernel(const float* __restrict__ c1,
                                                             const float* __restrict__ c2,
                                                             float* __restrict__ out,
                                                             int row_elems) {
    const int row = blockIdx.y;
    const int x   = blockIdx.x;
    const int tid = threadIdx.x;
    const size_t row_base = (size_t)row * row_elems;
    const int n4 = row_elems >> 2;            // 12544

    if (x < RSLICE) {
        // ---- Reduce slice x of conv1[row] (proven R3 body: dual-acc loop) ----
        const int per_slice = n4 / RSLICE;    // 1568
        const float4* p = reinterpret_cast<const float4*>(c1 + row_base) + x * per_slice;

        float s0 = 0.f, s1 = 0.f;
        int i = tid;
        for (; i + 256 < per_slice; i += 512) {
            float4 a = p[i];
            float4 b = p[i + 256];
            s0 += (a.x + a.y) + (a.z + a.w);
            s1 += (b.x + b.y) + (b.z + b.w);
        }
        if (i < per_slice) {
            float4 a = p[i];
            s0 += (a.x + a.y) + (a.z + a.w);
        }
        float s = s0 + s1;

        #pragma unroll
        for (int o = 16; o > 0; o >>= 1)
            s += __shfl_xor_sync(0xffffffffu, s, o);

        __shared__ float warp_sums[8];
        const int lane = tid & 31;
        const int wid  = tid >> 5;
        if (lane == 0) warp_sums[wid] = s;
        __syncthreads();

        if (tid == 0) {
            float t = 0.f;
            #pragma unroll
            for (int w = 0; w < 8; w++) t += warp_sums[w];

            d_partial[row * RSLICE + x] = t;
            __threadfence();
            unsigned int old = atomicAdd(&d_count[row], 1u);
            if (old == RSLICE - 1) {
                // Fixed-order sum -> deterministic mean.
                const volatile float* vp = d_partial + row * RSLICE;
                float sum = 0.f;
                #pragma unroll
                for (int k = 0; k < RSLICE; k++)
                    sum += vp[k];
                d_row_mean[row] = sum / (float)row_elems;
                d_count[row] = 0;            // self-reset for next replay
                __threadfence();
                d_ready[row] = 1;            // publish
            }
        }
    } else {
        // ---- Scale chunk (x - RSLICE) of conv2[row] ----
        const int chunk = x - RSLICE;
        const float4* src = reinterpret_cast<const float4*>(c2 + row_base);
        float4* dst       = reinterpret_cast<float4*>(out + row_base);
        const int idx = chunk * 256 + tid;

        // Issue the data load BEFORE waiting -> overlaps spin with memory.
        float4 v = src[idx];

        if (tid == 0) {
            while (d_ready[row] == 0) __nanosleep(64);
        }
        __syncthreads();
        __threadfence();  // order mean read after flag observation

        const float m = *((volatile float*)&d_row_mean[row]);
        v.x *= m; v.y *= m; v.z *= m; v.w *= m;
        dst[idx] = v;

        __syncthreads();
        if (tid == 0) {
            unsigned int o = atomicAdd(&d_done[row], 1u);
            if (o == SCHUNK - 1) {           // last scale block of this row
                d_ready[row] = 0;            // self-reset for next replay
                d_done[row] = 0;
            }
        }
    }
}

extern "C" void kernel_launch(void* const* d_in, const int* in_sizes, int n_in,
                              void* d_out, int out_size) {
    const float* c1 = (const float*)d_in[0];
    const float* c2 = (const float*)d_in[1];
    float* out = (float*)d_out;

    const int row_elems = in_sizes[0] / NROWS;  // 50176

    dim3 grid(XDIM, NROWS);                     // 57 x 256 = 14592 blocks
    fused_pipeline_kernel<<<grid, 256>>>(c1, c2, out, row_elems);
}

// round 9
// speedup vs baseline: 3.2252x; 3.2252x over previous
#include <cuda_runtime.h>
#include <cuda_bf16.h>

#define NROWS 256
#define NSLICE 8

// Scratch (no cudaMalloc). __device__ globals zero-init at module load.
__device__ float d_partial[NROWS * NSLICE];
__device__ float d_row_mean[NROWS];
__device__ unsigned int d_count[NROWS];

// Kernel 1: proven R3 reduce body (12.5us) + folded finalize (R4 mechanism).
// grid (NSLICE, 256). Block (s, row) reduces slice s of row `row`.
__global__ __launch_bounds__(256) void row_partial_kernel(const float* __restrict__ c1,
                                                          int row_elems) {
    const int row = blockIdx.y;
    const int slice = blockIdx.x;
    const int n4 = row_elems >> 2;          // 12544
    const int per_slice = n4 / NSLICE;      // 1568
    const float4* p = reinterpret_cast<const float4*>(c1 + (size_t)row * row_elems)
                      + slice * per_slice;

    float s0 = 0.f, s1 = 0.f;
    int i = threadIdx.x;
    for (; i + 256 < per_slice; i += 512) {
        float4 a = p[i];
        float4 b = p[i + 256];
        s0 += (a.x + a.y) + (a.z + a.w);
        s1 += (b.x + b.y) + (b.z + b.w);
    }
    if (i < per_slice) {
        float4 a = p[i];
        s0 += (a.x + a.y) + (a.z + a.w);
    }
    float s = s0 + s1;

    #pragma unroll
    for (int o = 16; o > 0; o >>= 1)
        s += __shfl_xor_sync(0xffffffffu, s, o);

    __shared__ float warp_sums[8];
    const int lane = threadIdx.x & 31;
    const int wid = threadIdx.x >> 5;
    if (lane == 0) warp_sums[wid] = s;
    __syncthreads();

    if (threadIdx.x == 0) {
        float t = 0.f;
        #pragma unroll
        for (int w = 0; w < 8; w++) t += warp_sums[w];

        d_partial[row * NSLICE + slice] = t;
        __threadfence();
        unsigned int old = atomicAdd(&d_count[row], 1u);
        if (old == NSLICE - 1) {
            // Last block for this row: fixed-order sum -> deterministic.
            const volatile float* vp = d_partial + row * NSLICE;
            float sum = 0.f;
            #pragma unroll
            for (int k = 0; k < NSLICE; k++)
                sum += vp[k];
            d_row_mean[row] = sum / (float)row_elems;
            d_count[row] = 0;  // self-reset for next graph replay
        }
    }

    // Signal PDL: this block's work is done -> secondary grid may dispatch.
    cudaTriggerProgrammaticLaunchCompletion();
}

// Kernel 2: proven R1 scale body, PDL-aware. Prefetch conv2 BEFORE the grid
// dependency sync (overlaps with primary tail), read mean only AFTER.
__global__ __launch_bounds__(256) void scale_kernel(const float* __restrict__ c2,
                                                    float* __restrict__ out,
                                                    int row_elems) {
    const int row = blockIdx.y;
    const size_t base = (size_t)row * row_elems;
    const float4* src = reinterpret_cast<const float4*>(c2 + base);
    float4* dst = reinterpret_cast<float4*>(out + base);
    const int i = blockIdx.x * blockDim.x + threadIdx.x;

    // Prefetch data that does NOT depend on the primary grid.
    float4 v = src[i];

    // Wait for primary grid completion (HW dependency, makes mean visible).
    cudaGridDependencySynchronize();

    const float m = d_row_mean[row];
    v.x *= m; v.y *= m; v.z *= m; v.w *= m;
    dst[i] = v;
}

extern "C" void kernel_launch(void* const* d_in, const int* in_sizes, int n_in,
                              void* d_out, int out_size) {
    const float* c1 = (const float*)d_in[0];
    const float* c2 = (const float*)d_in[1];
    float* out = (float*)d_out;

    const int row_elems = in_sizes[0] / NROWS;  // 50176

    dim3 rgrid(NSLICE, NROWS);                  // 8 x 256 = 2048 blocks
    row_partial_kernel<<<rgrid, 256>>>(c1, row_elems);

    // Secondary launch with programmatic stream serialization (PDL).
    const int n4_per_row = row_elems >> 2;      // 12544
    dim3 sgrid(n4_per_row / 256, NROWS);        // 49 x 256

    cudaLaunchConfig_t cfg = {};
    cfg.gridDim = sgrid;
    cfg.blockDim = dim3(256, 1, 1);
    cfg.dynamicSmemBytes = 0;
    cfg.stream = 0;
    cudaLaunchAttribute attrs[1];
    attrs[0].id = cudaLaunchAttributeProgrammaticStreamSerialization;
    attrs[0].val.programmaticStreamSerializationAllowed = 1;
    cfg.attrs = attrs;
    cfg.numAttrs = 1;

    cudaLaunchKernelEx(&cfg, scale_kernel, c2, out, row_elems);
}